// round 2
// baseline (speedup 1.0000x reference)
#include <cuda_runtime.h>

#define T_ 512
#define B_ 256
#define D_ 128
#define H_ 256
#define P_ 128
#define NBLK 128
#define NTHR 256
#define PPAD 132     // d2x kernel proto row stride (floats): 132*4/16=33 odd -> conflict-free LDS.128
#define PHPAD 260    // main kernel proto_h row stride: 260*4/16=65 odd -> conflict-free LDS.128

// ---------------- device scratch (static globals; no allocation) ----------------
__device__ float g_d2x[T_ * B_ * P_];          // 64 MB: x-part of RBF distances
__device__ float g_k[B_ * P_];                 // per-step kernel features
__device__ float g_h[B_ * H_];                 // recurrent hidden state
__device__ volatile unsigned g_flag[NBLK];     // grid barrier flags (monotonic across replays)

typedef unsigned long long ull;

__device__ __forceinline__ ull pk2(float a, float b) {
    ull r; asm("mov.b64 %0, {%1, %2};" : "=l"(r) : "f"(a), "f"(b)); return r;
}
__device__ __forceinline__ void upk2(ull v, float& a, float& b) {
    asm("mov.b64 {%0, %1}, %2;" : "=f"(a), "=f"(b) : "l"(v));
}
__device__ __forceinline__ ull ffma2(ull a, ull b, ull c) {
    ull d; asm("fma.rn.f32x2 %0, %1, %2, %3;" : "=l"(d) : "l"(a), "l"(b), "l"(c)); return d;
}
#define NEG1X2 0xBF800000BF800000ULL

__device__ __forceinline__ float sigmf(float x) { return 1.0f / (1.0f + __expf(-x)); }

// =====================================================================
// Kernel 1: d2x[t][b][p] = sum_{d<128} (x[t,b,d] - proto[p,d])^2
// grid (512, 16); fully parallel, fma-bound.
// =====================================================================
#define D2X_SMEM ((P_ * PPAD + 16 * D_) * 4)

__global__ void __launch_bounds__(NTHR) d2x_kernel(const float* __restrict__ x,
                                                   const float* __restrict__ proto) {
    extern __shared__ float sm[];
    float* ps = sm;               // [128][PPAD]
    float* xs = sm + P_ * PPAD;   // [16][128]
    const int t = blockIdx.x, b0 = blockIdx.y * 16;
    const int tid = threadIdx.x;

    for (int i = tid; i < P_ * D_; i += NTHR) {
        int p = i >> 7, d = i & 127;
        ps[p * PPAD + d] = proto[p * (D_ + H_) + d];
    }
    for (int i = tid; i < 16 * D_; i += NTHR) {
        int bb = i >> 7, d = i & 127;
        xs[i] = x[((size_t)(t * B_) + b0 + bb) * D_ + d];
    }
    __syncthreads();

    const int p = tid & 127, bg = tid >> 7;   // thread: 1 prototype x 8 batch rows
    ull acc[8];
    #pragma unroll
    for (int bb = 0; bb < 8; bb++) acc[bb] = 0ULL;
    const float4* pp = (const float4*)(ps + p * PPAD);
    const float*  xb = xs + bg * 8 * D_;

    #pragma unroll 4
    for (int i = 0; i < 32; i++) {
        float4 pv = pp[i];
        ull pA = pk2(pv.x, pv.y), pB = pk2(pv.z, pv.w);
        #pragma unroll
        for (int bb = 0; bb < 8; bb++) {
            float4 xv = *(const float4*)(xb + bb * D_ + 4 * i);
            ull dA = ffma2(pA, NEG1X2, pk2(xv.x, xv.y));   // x - p (exact)
            ull dB = ffma2(pB, NEG1X2, pk2(xv.z, xv.w));
            acc[bb] = ffma2(dA, dA, acc[bb]);
            acc[bb] = ffma2(dB, dB, acc[bb]);
        }
    }
    #pragma unroll
    for (int bb = 0; bb < 8; bb++) {
        float a, b; upk2(acc[bb], a, b);
        g_d2x[((size_t)t * B_ + b0 + bg * 8 + bb) * P_ + p] = a + b;
    }
}

// =====================================================================
// Grid barrier: release-fence + per-block flag + parallel poll.
// Targets are monotonic across graph replays (flags never reset).
// =====================================================================
__device__ __forceinline__ void gbar(unsigned target) {
    __threadfence();                 // release: publish this block's phase writes
    __syncthreads();
    if (threadIdx.x == 0) g_flag[blockIdx.x] = target;          // volatile store
    if (threadIdx.x < NBLK) {
        while ((int)(g_flag[threadIdx.x] - target) < 0) { }     // volatile poll (L2)
    }
    __syncthreads();
}

// =====================================================================
// Kernel 2: persistent recurrent kernel. 128 blocks, 1/SM, all resident.
// Phase K: block j owns batch rows {2j,2j+1}. Phase G: hidden cols {2j,2j+1}.
// =====================================================================
#define SM_WS_OFF  (P_ * PHPAD)             // 33280 floats
#define SM_HS_OFF  (SM_WS_OFF + 4 * P_ * 2) // ws: 4 gates x 128 x float2
#define SM_RED_OFF (SM_HS_OFF + 2 * H_)
#define SM_TOT_F   (SM_RED_OFF + 2 * P_)
#define MAIN_SMEM  (SM_TOT_F * 4)           // 140288 bytes

__global__ void __launch_bounds__(NTHR, 1) qlstm_kernel(
    const float* __restrict__ proto,
    const float* __restrict__ Wf, const float* __restrict__ bfv,
    const float* __restrict__ Wi, const float* __restrict__ biv,
    const float* __restrict__ Wg, const float* __restrict__ bgv,
    const float* __restrict__ Wo, const float* __restrict__ bov,
    float* __restrict__ out)
{
    extern __shared__ float sm[];
    float* ph  = sm;                 // proto_h [128][PHPAD]
    float* ws  = sm + SM_WS_OFF;     // [4][128] float2 {W[hc0][p], W[hc1][p]}
    float* hs  = sm + SM_HS_OFF;     // staged h rows [2][256]
    float* red = sm + SM_RED_OFF;    // [128] float2 partial d2

    const int tid = threadIdx.x;
    const int j   = blockIdx.x;
    const int hc0 = 2 * j;           // also this block's first batch row in phase K

    const unsigned base = g_flag[j]; // own flag: stable; equal across blocks at launch

    // ---- resident data ----
    for (int i = tid; i < P_ * H_; i += NTHR) {
        int p = i >> 8, d = i & 255;
        ph[p * PHPAD + d] = proto[p * (D_ + H_) + D_ + d];
    }
    {
        const float* Wt[4] = {Wf, Wi, Wg, Wo};
        for (int i = tid; i < 4 * P_; i += NTHR) {
            int g = i >> 7, p = i & 127;
            ws[2 * i]     = Wt[g][hc0 * P_ + p];
            ws[2 * i + 1] = Wt[g][(hc0 + 1) * P_ + p];
        }
    }
    const float2 bF = make_float2(bfv[hc0], bfv[hc0 + 1]);
    const float2 bI = make_float2(biv[hc0], biv[hc0 + 1]);
    const float2 bG = make_float2(bgv[hc0], bgv[hc0 + 1]);
    const float2 bO = make_float2(bov[hc0], bov[hc0 + 1]);

    float c0 = 0.0f, c1 = 0.0f;      // cell state: this thread's batch row, 2 hidden cols
    __syncthreads();

    const int pk   = tid & 127;      // phase-K prototype index
    const int half = tid >> 7;       // phase-K d-half (warps 0-3: half 0; 4-7: half 1)
    unsigned bar = 0;

    for (int t = 0; t < T_; t++) {
        // ================= Phase K =================
        if (t > 0) {
            float2 hv = __ldcg(((const float2*)(g_h + hc0 * H_)) + tid);   // rows 2j,2j+1 (L2, bypass L1)
            ((float2*)hs)[tid] = hv;
            __stcs(((float2*)(out + ((size_t)(t - 1) * B_ + hc0) * H_)) + tid, hv);  // emit out[t-1]
        } else {
            ((float2*)hs)[tid] = make_float2(0.0f, 0.0f);
        }
        float d2x0 = 0.0f, d2x1 = 0.0f;
        if (!half) {
            d2x0 = g_d2x[((size_t)t * B_ + hc0)     * P_ + pk];
            d2x1 = g_d2x[((size_t)t * B_ + hc0 + 1) * P_ + pk];
        }
        __syncthreads();

        ull a0 = 0ULL, a1 = 0ULL;
        const float4* pr = (const float4*)(ph + pk * PHPAD + half * 128);
        const float4* h0 = (const float4*)(hs + half * 128);
        const float4* h1 = (const float4*)(hs + 256 + half * 128);
        #pragma unroll 8
        for (int i = 0; i < 32; i++) {
            float4 pv = pr[i];
            float4 u = h0[i], v = h1[i];
            ull pA = pk2(pv.x, pv.y), pB = pk2(pv.z, pv.w);
            ull dA0 = ffma2(pA, NEG1X2, pk2(u.x, u.y));
            ull dB0 = ffma2(pB, NEG1X2, pk2(u.z, u.w));
            a0 = ffma2(dA0, dA0, a0); a0 = ffma2(dB0, dB0, a0);
            ull dA1 = ffma2(pA, NEG1X2, pk2(v.x, v.y));
            ull dB1 = ffma2(pB, NEG1X2, pk2(v.z, v.w));
            a1 = ffma2(dA1, dA1, a1); a1 = ffma2(dB1, dB1, a1);
        }
        float s0a, s0b, s1a, s1b;
        upk2(a0, s0a, s0b); upk2(a1, s1a, s1b);
        float s0 = s0a + s0b, s1 = s1a + s1b;

        if (half) ((float2*)red)[pk] = make_float2(s0, s1);
        __syncthreads();
        if (!half) {
            float2 r = ((float2*)red)[pk];
            g_k[hc0 * P_ + pk]       = __expf(-(d2x0 + s0 + r.x));
            g_k[(hc0 + 1) * P_ + pk] = __expf(-(d2x1 + s1 + r.y));
        }
        gbar(base + (++bar));   // k ready everywhere

        // ================= Phase G =================
        // thread handles batch row b = tid, hidden cols hc0, hc0+1
        const float4* kr4 = (const float4*)(g_k + tid * P_);
        float4 kr[32];
        #pragma unroll
        for (int q = 0; q < 32; q++) kr[q] = __ldcg(kr4 + q);   // full k row, L1-bypass

        ull accf = 0ULL, acci = 0ULL, accg = 0ULL, acco = 0ULL;
        const ulonglong2* wfU = (const ulonglong2*)(ws);
        const ulonglong2* wiU = (const ulonglong2*)(ws + 256);
        const ulonglong2* wgU = (const ulonglong2*)(ws + 512);
        const ulonglong2* woU = (const ulonglong2*)(ws + 768);
        #pragma unroll 8
        for (int q = 0; q < 32; q++) {
            float4 kv = kr[q];
            ull k0 = pk2(kv.x, kv.x), k1 = pk2(kv.y, kv.y);
            ull k2 = pk2(kv.z, kv.z), k3 = pk2(kv.w, kv.w);
            ulonglong2 wa;
            wa = wfU[2 * q];     accf = ffma2(k0, wa.x, accf); accf = ffma2(k1, wa.y, accf);
            wa = wfU[2 * q + 1]; accf = ffma2(k2, wa.x, accf); accf = ffma2(k3, wa.y, accf);
            wa = wiU[2 * q];     acci = ffma2(k0, wa.x, acci); acci = ffma2(k1, wa.y, acci);
            wa = wiU[2 * q + 1]; acci = ffma2(k2, wa.x, acci); acci = ffma2(k3, wa.y, acci);
            wa = wgU[2 * q];     accg = ffma2(k0, wa.x, accg); accg = ffma2(k1, wa.y, accg);
            wa = wgU[2 * q + 1]; accg = ffma2(k2, wa.x, accg); accg = ffma2(k3, wa.y, accg);
            wa = woU[2 * q];     acco = ffma2(k0, wa.x, acco); acco = ffma2(k1, wa.y, acco);
            wa = woU[2 * q + 1]; acco = ffma2(k2, wa.x, acco); acco = ffma2(k3, wa.y, acco);
        }
        float zf0, zf1, zi0, zi1, zg0, zg1, zo0, zo1;
        upk2(accf, zf0, zf1); upk2(acci, zi0, zi1);
        upk2(accg, zg0, zg1); upk2(acco, zo0, zo1);

        float f0 = sigmf(zf0 + bF.x), f1 = sigmf(zf1 + bF.y);
        float i0 = sigmf(zi0 + bI.x), i1 = sigmf(zi1 + bI.y);
        float gg0 = tanhf(zg0 + bG.x), gg1 = tanhf(zg1 + bG.y);
        float o0 = sigmf(zo0 + bO.x), o1 = sigmf(zo1 + bO.y);
        c0 = f0 * c0 + i0 * gg0;
        c1 = f1 * c1 + i1 * gg1;
        float hn0 = o0 * tanhf(c0), hn1 = o1 * tanhf(c1);
        *((float2*)(g_h + tid * H_ + hc0)) = make_float2(hn0, hn1);

        gbar(base + (++bar));   // h ready everywhere
    }

    // ---- epilogue: out[T-1], hx (rows), cx (own cells) ----
    {
        float2 hv = __ldcg(((const float2*)(g_h + hc0 * H_)) + tid);
        __stcs(((float2*)(out + ((size_t)(T_ - 1) * B_ + hc0) * H_)) + tid, hv);
        __stcs(((float2*)(out + (size_t)T_ * B_ * H_ + hc0 * H_)) + tid, hv);
    }
    __stcs((float2*)(out + (size_t)T_ * B_ * H_ + (size_t)B_ * H_ + (size_t)tid * H_ + hc0),
           make_float2(c0, c1));
}

// =====================================================================
// launch
// =====================================================================
extern "C" void kernel_launch(void* const* d_in, const int* in_sizes, int n_in,
                              void* d_out, int out_size) {
    const float* x     = (const float*)d_in[0];
    const float* proto = (const float*)d_in[1];
    const float* Wf    = (const float*)d_in[2];
    const float* bf    = (const float*)d_in[3];
    const float* Wi    = (const float*)d_in[4];
    const float* bi    = (const float*)d_in[5];
    const float* Wg    = (const float*)d_in[6];
    const float* bg    = (const float*)d_in[7];
    const float* Wo    = (const float*)d_in[8];
    const float* bo    = (const float*)d_in[9];
    float* out = (float*)d_out;

    cudaFuncSetAttribute(d2x_kernel,  cudaFuncAttributeMaxDynamicSharedMemorySize, D2X_SMEM);
    cudaFuncSetAttribute(qlstm_kernel, cudaFuncAttributeMaxDynamicSharedMemorySize, MAIN_SMEM);

    d2x_kernel<<<dim3(T_, B_ / 16), NTHR, D2X_SMEM>>>(x, proto);
    qlstm_kernel<<<NBLK, NTHR, MAIN_SMEM>>>(proto, Wf, bf, Wi, bi, Wg, bg, Wo, bo, out);
}

// round 3
// speedup vs baseline: 1.3021x; 1.3021x over previous
#include <cuda_runtime.h>
#include <cuda_fp16.h>

#define T_ 512
#define B_ 256
#define D_ 128
#define H_ 256
#define P_ 128
#define NBLK 128
#define NT1 256      // d2x kernel threads
#define NT2 512      // main kernel threads
#define PPAD 132     // d2x proto row stride: conflict-free LDS.128
#define PHPAD 260    // main proto_h row stride: conflict-free LDS.128

// ---------------- device scratch (static globals; no allocation) ----------------
__device__ float g_d2x[T_ * B_ * P_];              // 64 MB: x-part of RBF distances
__device__ __half g_kh[B_ * P_];                   // per-step kernel features (fp16)
__device__ float g_h[B_ * H_];                     // recurrent hidden state
__device__ __align__(16) unsigned g_flag[NBLK];    // barrier flags (monotonic across replays)

typedef unsigned long long ull;

__device__ __forceinline__ ull pk2(float a, float b) {
    ull r; asm("mov.b64 %0, {%1, %2};" : "=l"(r) : "f"(a), "f"(b)); return r;
}
__device__ __forceinline__ void upk2(ull v, float& a, float& b) {
    asm("mov.b64 {%0, %1}, %2;" : "=f"(a), "=f"(b) : "l"(v));
}
__device__ __forceinline__ ull ffma2(ull a, ull b, ull c) {
    ull d; asm("fma.rn.f32x2 %0, %1, %2, %3;" : "=l"(d) : "l"(a), "l"(b), "l"(c)); return d;
}
#define NEG1X2 0xBF800000BF800000ULL

__device__ __forceinline__ float sigmf(float x) { return 1.0f / (1.0f + __expf(-x)); }

__device__ __forceinline__ uint4 ldv4(const unsigned* p) {
    uint4 v;
    asm volatile("ld.volatile.global.v4.u32 {%0,%1,%2,%3}, [%4];"
                 : "=r"(v.x), "=r"(v.y), "=r"(v.z), "=r"(v.w) : "l"(p));
    return v;
}
__device__ __forceinline__ ull h2tof2(unsigned u) {      // half2 -> packed f32x2
    __half2 h = *reinterpret_cast<__half2*>(&u);
    float2 f = __half22float2(h);
    return pk2(f.x, f.y);
}

// =====================================================================
// Kernel 1: d2x[t][b][p] = sum_{d<128} (x[t,b,d] - proto[p,d])^2
// =====================================================================
#define D2X_SMEM ((P_ * PPAD + 16 * D_) * 4)

__global__ void __launch_bounds__(NT1) d2x_kernel(const float* __restrict__ x,
                                                  const float* __restrict__ proto) {
    extern __shared__ float sm[];
    float* ps = sm;               // [128][PPAD]
    float* xs = sm + P_ * PPAD;   // [16][128]
    const int t = blockIdx.x, b0 = blockIdx.y * 16;
    const int tid = threadIdx.x;

    for (int i = tid; i < P_ * D_; i += NT1) {
        int p = i >> 7, d = i & 127;
        ps[p * PPAD + d] = proto[p * (D_ + H_) + d];
    }
    for (int i = tid; i < 16 * D_; i += NT1) {
        int bb = i >> 7, d = i & 127;
        xs[i] = x[((size_t)(t * B_) + b0 + bb) * D_ + d];
    }
    __syncthreads();

    const int p = tid & 127, bg = tid >> 7;
    ull acc[8];
    #pragma unroll
    for (int bb = 0; bb < 8; bb++) acc[bb] = 0ULL;
    const float4* pp = (const float4*)(ps + p * PPAD);
    const float*  xb = xs + bg * 8 * D_;

    #pragma unroll 4
    for (int i = 0; i < 32; i++) {
        float4 pv = pp[i];
        ull pA = pk2(pv.x, pv.y), pB = pk2(pv.z, pv.w);
        #pragma unroll
        for (int bb = 0; bb < 8; bb++) {
            float4 xv = *(const float4*)(xb + bb * D_ + 4 * i);
            ull dA = ffma2(pA, NEG1X2, pk2(xv.x, xv.y));
            ull dB = ffma2(pB, NEG1X2, pk2(xv.z, xv.w));
            acc[bb] = ffma2(dA, dA, acc[bb]);
            acc[bb] = ffma2(dB, dB, acc[bb]);
        }
    }
    #pragma unroll
    for (int bb = 0; bb < 8; bb++) {
        float a, b; upk2(acc[bb], a, b);
        g_d2x[((size_t)t * B_ + b0 + bg * 8 + bb) * P_ + p] = a + b;
    }
}

// =====================================================================
// Grid barrier: release fence + per-block flag; warp 0 polls all 128
// flags via vectorized volatile loads. Monotonic targets.
// =====================================================================
__device__ __forceinline__ void gbar(unsigned target) {
    __threadfence();
    __syncthreads();
    if (threadIdx.x == 0)
        *(volatile unsigned*)&g_flag[blockIdx.x] = target;
    if (threadIdx.x < 32) {
        const unsigned* fp = g_flag + threadIdx.x * 4;
        for (;;) {
            uint4 v = ldv4(fp);
            if ((int)(v.x - target) >= 0 && (int)(v.y - target) >= 0 &&
                (int)(v.z - target) >= 0 && (int)(v.w - target) >= 0) break;
        }
    }
    __syncthreads();
}

// =====================================================================
// Kernel 2: persistent recurrent kernel. 128 blocks x 512 threads.
// Phase K: block j owns batch rows {2j,2j+1}; thread=(p, d-quarter).
// Phase G: block j owns hidden cols {2j,2j+1}; thread=(b, p-half).
// =====================================================================
#define SM_WS_OFF  (P_ * PHPAD)               // 33280
#define SM_HS_OFF  (SM_WS_OFF + 4 * 2 * P_)   // ws: [gate][col][p] = 1024 floats
#define SM_RED_OFF (SM_HS_OFF + 2 * H_)       // hs: 512 floats
#define SM_ZR_OFF  (SM_RED_OFF + 3 * 2 * P_)  // red3: 3 quarters x 128 float2
#define SM_TOT_F   (SM_ZR_OFF + 8 * B_)       // zr: [8 gatecol][256 b] floats
#define MAIN_SMEM  (SM_TOT_F * 4)             // 150528 bytes

__global__ void __launch_bounds__(NT2, 1) qlstm_kernel(
    const float* __restrict__ proto,
    const float* __restrict__ Wf, const float* __restrict__ bfv,
    const float* __restrict__ Wi, const float* __restrict__ biv,
    const float* __restrict__ Wg, const float* __restrict__ bgv,
    const float* __restrict__ Wo, const float* __restrict__ bov,
    float* __restrict__ out)
{
    extern __shared__ float sm[];
    float* ph   = sm;                  // proto_h [128][PHPAD]
    float* ws   = sm + SM_WS_OFF;      // [4 gate][2 col][128 p]
    float* hs   = sm + SM_HS_OFF;      // staged h rows [2][256]
    float* red3 = sm + SM_RED_OFF;     // [3][128] float2 partial d2
    float* zr   = sm + SM_ZR_OFF;      // [8][256] gate partials

    const int tid = threadIdx.x;
    const int j   = blockIdx.x;
    const int hc0 = 2 * j;

    const unsigned base = *(volatile unsigned*)&g_flag[j];

    // ---- resident data ----
    for (int i = tid; i < P_ * H_; i += NT2) {
        int p = i >> 8, d = i & 255;
        ph[p * PHPAD + d] = proto[p * (D_ + H_) + D_ + d];
    }
    {
        const float* Wt[4] = {Wf, Wi, Wg, Wo};
        for (int i = tid; i < 4 * 2 * P_; i += NT2) {
            int g = i >> 8, c = (i >> 7) & 1, p = i & 127;
            ws[i] = Wt[g][(hc0 + c) * P_ + p];
        }
    }
    const float2 bF = make_float2(bfv[hc0], bfv[hc0 + 1]);
    const float2 bI = make_float2(biv[hc0], biv[hc0 + 1]);
    const float2 bG = make_float2(bgv[hc0], bgv[hc0 + 1]);
    const float2 bO = make_float2(bov[hc0], bov[hc0 + 1]);

    float c0 = 0.0f, c1 = 0.0f;          // cell state (threads tid<256: row b=tid)
    __syncthreads();

    const int pk  = tid & 127;           // phase-K prototype
    const int qk  = tid >> 7;            // phase-K d-quarter (0..3)
    const int bG_ = tid & 255;           // phase-G batch row
    const int ph2 = tid >> 8;            // phase-G p-half (0/1)
    unsigned bar = 0;

    for (int t = 0; t < T_; t++) {
        // ================= Phase K =================
        if (t > 0) {
            float hv = __ldcg(g_h + hc0 * H_ + tid);   // rows 2j,2j+1 (512 floats)
            hs[tid] = hv;
            __stcs(out + ((size_t)(t - 1) * B_ + hc0) * H_ + tid, hv);
        } else {
            hs[tid] = 0.0f;
        }
        float d2x0 = 0.0f, d2x1 = 0.0f;
        if (qk == 0) {
            d2x0 = g_d2x[((size_t)t * B_ + hc0)     * P_ + pk];
            d2x1 = g_d2x[((size_t)t * B_ + hc0 + 1) * P_ + pk];
        }
        __syncthreads();

        ull a0 = 0ULL, a1 = 0ULL;
        const float4* pr = (const float4*)(ph + pk * PHPAD + qk * 64);
        const float4* h0 = (const float4*)(hs + qk * 64);
        const float4* h1 = (const float4*)(hs + 256 + qk * 64);
        #pragma unroll
        for (int i = 0; i < 16; i++) {
            float4 pv = pr[i];
            float4 u = h0[i], v = h1[i];
            ull pA = pk2(pv.x, pv.y), pB = pk2(pv.z, pv.w);
            ull dA0 = ffma2(pA, NEG1X2, pk2(u.x, u.y));
            ull dB0 = ffma2(pB, NEG1X2, pk2(u.z, u.w));
            a0 = ffma2(dA0, dA0, a0); a0 = ffma2(dB0, dB0, a0);
            ull dA1 = ffma2(pA, NEG1X2, pk2(v.x, v.y));
            ull dB1 = ffma2(pB, NEG1X2, pk2(v.z, v.w));
            a1 = ffma2(dA1, dA1, a1); a1 = ffma2(dB1, dB1, a1);
        }
        float s0a, s0b, s1a, s1b;
        upk2(a0, s0a, s0b); upk2(a1, s1a, s1b);
        float s0 = s0a + s0b, s1 = s1a + s1b;

        if (qk) ((float2*)red3)[(qk - 1) * P_ + pk] = make_float2(s0, s1);
        __syncthreads();
        if (qk == 0) {
            float2 r1 = ((float2*)red3)[pk];
            float2 r2 = ((float2*)red3)[P_ + pk];
            float2 r3 = ((float2*)red3)[2 * P_ + pk];
            float k0 = __expf(-(d2x0 + s0 + r1.x + r2.x + r3.x));
            float k1 = __expf(-(d2x1 + s1 + r1.y + r2.y + r3.y));
            g_kh[hc0 * P_ + pk]       = __float2half_rn(k0);
            g_kh[(hc0 + 1) * P_ + pk] = __float2half_rn(k1);
        }
        gbar(base + (++bar));   // k ready everywhere

        // ================= Phase G =================
        // thread: batch row bG_, p-range [ph2*64, ph2*64+64)
        uint4 kv[8];
        {
            const uint4* kp = (const uint4*)(g_kh + bG_ * P_ + ph2 * 64);
            #pragma unroll
            for (int i = 0; i < 8; i++) kv[i] = __ldcg(kp + i);
        }
        ull acc[8];
        #pragma unroll
        for (int gc = 0; gc < 8; gc++) acc[gc] = 0ULL;
        const float4* w4 = (const float4*)ws;
        #pragma unroll
        for (int i = 0; i < 8; i++) {
            ull k01 = h2tof2(kv[i].x), k23 = h2tof2(kv[i].y);
            ull k45 = h2tof2(kv[i].z), k67 = h2tof2(kv[i].w);
            #pragma unroll
            for (int gc = 0; gc < 8; gc++) {
                float4 wa = w4[gc * 32 + ph2 * 16 + 2 * i];
                float4 wb = w4[gc * 32 + ph2 * 16 + 2 * i + 1];
                acc[gc] = ffma2(k01, pk2(wa.x, wa.y), acc[gc]);
                acc[gc] = ffma2(k23, pk2(wa.z, wa.w), acc[gc]);
                acc[gc] = ffma2(k45, pk2(wb.x, wb.y), acc[gc]);
                acc[gc] = ffma2(k67, pk2(wb.z, wb.w), acc[gc]);
            }
        }
        float z[8];
        #pragma unroll
        for (int gc = 0; gc < 8; gc++) {
            float a, b; upk2(acc[gc], a, b);
            z[gc] = a + b;
        }
        if (ph2) {
            #pragma unroll
            for (int gc = 0; gc < 8; gc++) zr[gc * B_ + bG_] = z[gc];
        }
        __syncthreads();
        if (!ph2) {
            #pragma unroll
            for (int gc = 0; gc < 8; gc++) z[gc] += zr[gc * B_ + bG_];
            float f0 = sigmf(z[0] + bF.x), f1 = sigmf(z[1] + bF.y);
            float i0 = sigmf(z[2] + bI.x), i1 = sigmf(z[3] + bI.y);
            float g0 = tanhf(z[4] + bG.x), g1 = tanhf(z[5] + bG.y);
            float o0 = sigmf(z[6] + bO.x), o1 = sigmf(z[7] + bO.y);
            c0 = f0 * c0 + i0 * g0;
            c1 = f1 * c1 + i1 * g1;
            float hn0 = o0 * tanhf(c0), hn1 = o1 * tanhf(c1);
            __stcg((float2*)(g_h + bG_ * H_ + hc0), make_float2(hn0, hn1));
        }
        gbar(base + (++bar));   // h ready everywhere
    }

    // ---- epilogue: out[T-1], hx, cx ----
    {
        float hv = __ldcg(g_h + hc0 * H_ + tid);
        __stcs(out + ((size_t)(T_ - 1) * B_ + hc0) * H_ + tid, hv);
        __stcs(out + (size_t)T_ * B_ * H_ + hc0 * H_ + tid, hv);
    }
    if (tid < B_) {
        __stcs((float2*)(out + (size_t)T_ * B_ * H_ + (size_t)B_ * H_ + (size_t)tid * H_ + hc0),
               make_float2(c0, c1));
    }
}

// =====================================================================
// launch
// =====================================================================
extern "C" void kernel_launch(void* const* d_in, const int* in_sizes, int n_in,
                              void* d_out, int out_size) {
    const float* x     = (const float*)d_in[0];
    const float* proto = (const float*)d_in[1];
    const float* Wf    = (const float*)d_in[2];
    const float* bf    = (const float*)d_in[3];
    const float* Wi    = (const float*)d_in[4];
    const float* bi    = (const float*)d_in[5];
    const float* Wg    = (const float*)d_in[6];
    const float* bg    = (const float*)d_in[7];
    const float* Wo    = (const float*)d_in[8];
    const float* bo    = (const float*)d_in[9];
    float* out = (float*)d_out;

    cudaFuncSetAttribute(d2x_kernel,   cudaFuncAttributeMaxDynamicSharedMemorySize, D2X_SMEM);
    cudaFuncSetAttribute(qlstm_kernel, cudaFuncAttributeMaxDynamicSharedMemorySize, MAIN_SMEM);

    d2x_kernel<<<dim3(T_, B_ / 16), NT1, D2X_SMEM>>>(x, proto);
    qlstm_kernel<<<NBLK, NT2, MAIN_SMEM>>>(proto, Wf, bf, Wi, bi, Wg, bg, Wo, bo, out);
}

// round 8
// speedup vs baseline: 3.5191x; 2.7027x over previous
#include <cuda_runtime.h>
#include <cuda_fp16.h>

#define T_ 512
#define B_ 256
#define D_ 128
#define H_ 256
#define P_ 128
#define NBLK 128
#define NT1 256
#define NT2 512
#define PPAD 132

// ---------------- device scratch (static globals; no allocation) ----------------
__device__ float  g_d2x[T_ * B_ * P_];     // 64 MB: x-part of RBF distances
__device__ __half2 g_Whs[512 * 64];        // W fp16, smem-resident half: [cp][p<64]
__device__ __half2 g_Wst[512 * 64];        // W fp16, streamed half: [(p-64)/4][cp][p&3] (uint4-coalesced)

typedef unsigned long long ull;

__device__ __forceinline__ ull pk2(float a, float b) {
    ull r; asm("mov.b64 %0, {%1, %2};" : "=l"(r) : "f"(a), "f"(b)); return r;
}
__device__ __forceinline__ void upk2(ull v, float& a, float& b) {
    asm("mov.b64 {%0, %1}, %2;" : "=f"(a), "=f"(b) : "l"(v));
}
__device__ __forceinline__ ull ffma2(ull a, ull b, ull c) {
    ull d; asm("fma.rn.f32x2 %0, %1, %2, %3;" : "=l"(d) : "l"(a), "l"(b), "l"(c)); return d;
}
#define NEG1X2 0xBF800000BF800000ULL

__device__ __forceinline__ float sigmf(float x) { return 1.0f / (1.0f + __expf(-x)); }

// =====================================================================
// Kernel 0: pack W (fp32 [4][256 cols][128 p]) into fp16 col-pair layouts.
// cp = g*128 + c covers cols (2c, 2c+1) of gate g. half2 = {W[2c][p], W[2c+1][p]}.
//   p <  64 -> g_Whs[cp*64 + p]
//   p >= 64 -> g_Wst[((p-64)>>2)*2048 + cp*4 + (p&3)]  (16B groups of 4 p, lane-major cp)
// =====================================================================
__global__ void __launch_bounds__(NT2) prep_kernel(
    const float* __restrict__ Wf, const float* __restrict__ Wi,
    const float* __restrict__ Wg, const float* __restrict__ Wo)
{
    int i = blockIdx.x * NT2 + threadIdx.x;          // 128 blocks x 512 = 65536
    int g = i >> 14, c = (i >> 7) & 127, p = i & 127;
    const float* W = (g == 0) ? Wf : (g == 1) ? Wi : (g == 2) ? Wg : Wo;
    __half2 v = __floats2half2_rn(W[(2 * c) * P_ + p], W[(2 * c + 1) * P_ + p]);
    int cp = g * 128 + c;
    if (p < 64) g_Whs[cp * 64 + p] = v;
    else        g_Wst[((p - 64) >> 2) * 2048 + cp * 4 + (p & 3)] = v;
}

// =====================================================================
// Kernel 1: d2x[t][b][p] = sum_{d<128} (x[t,b,d] - proto[p,d])^2
// =====================================================================
#define D2X_SMEM ((P_ * PPAD + 16 * D_) * 4)

__global__ void __launch_bounds__(NT1) d2x_kernel(const float* __restrict__ x,
                                                  const float* __restrict__ proto) {
    extern __shared__ float sm[];
    float* ps = sm;
    float* xs = sm + P_ * PPAD;
    const int t = blockIdx.x, b0 = blockIdx.y * 16;
    const int tid = threadIdx.x;

    for (int i = tid; i < P_ * D_; i += NT1) {
        int p = i >> 7, d = i & 127;
        ps[p * PPAD + d] = proto[p * (D_ + H_) + d];
    }
    for (int i = tid; i < 16 * D_; i += NT1) {
        int bb = i >> 7, d = i & 127;
        xs[i] = x[((size_t)(t * B_) + b0 + bb) * D_ + d];
    }
    __syncthreads();

    const int p = tid & 127, bg = tid >> 7;
    ull acc[8];
    #pragma unroll
    for (int bb = 0; bb < 8; bb++) acc[bb] = 0ULL;
    const float4* pp = (const float4*)(ps + p * PPAD);
    const float*  xb = xs + bg * 8 * D_;

    #pragma unroll 4
    for (int i = 0; i < 32; i++) {
        float4 pv = pp[i];
        ull pA = pk2(pv.x, pv.y), pB = pk2(pv.z, pv.w);
        #pragma unroll
        for (int bb = 0; bb < 8; bb++) {
            float4 xv = *(const float4*)(xb + bb * D_ + 4 * i);
            ull dA = ffma2(pA, NEG1X2, pk2(xv.x, xv.y));
            ull dB = ffma2(pB, NEG1X2, pk2(xv.z, xv.w));
            acc[bb] = ffma2(dA, dA, acc[bb]);
            acc[bb] = ffma2(dB, dB, acc[bb]);
        }
    }
    #pragma unroll
    for (int bb = 0; bb < 8; bb++) {
        float a, b; upk2(acc[bb], a, b);
        g_d2x[((size_t)t * B_ + b0 + bg * 8 + bb) * P_ + p] = a + b;
    }
}

// =====================================================================
// Kernel 2: barrier-free recurrent kernel. 128 blocks x 512 threads.
// Block j owns batch rows {2j, 2j+1} for all 512 steps. No grid sync.
// Phase K: thread = (d-quarter dq, prototype p). Phase G: thread = cp.
// =====================================================================
// smem byte offsets
#define SO_PH   0                      // proto_h fp16 transposed [128 d2][128 p] half2: 65536 B
#define SO_W    65536                  // W smem half [512 cp][68 pad half2]: 139264 B
#define SO_H    204800                 // h [2][256] f32: 2048 B
#define SO_KQ   206848                 // kq [128] float4 {k0,k0,k1,k1}: 2048 B
#define SO_RED  208896                 // red [3][128] float2: 3072 B
#define SO_Z    211968                 // z [4 g][2 r][128 c] float2: 8192 B
#define SO_B    220160                 // bias [4][256] f32: 4096 B
#define MAIN_SMEM 224256

__global__ void __launch_bounds__(NT2, 1) qlstm_kernel(
    const float* __restrict__ proto,
    const float* __restrict__ bfv, const float* __restrict__ biv,
    const float* __restrict__ bgv, const float* __restrict__ bov,
    float* __restrict__ out)
{
    extern __shared__ char smraw[];
    __half2* s_ph = (__half2*)(smraw + SO_PH);
    __half2* s_w  = (__half2*)(smraw + SO_W);
    float*   s_h  = (float*)(smraw + SO_H);
    float*   s_kq = (float*)(smraw + SO_KQ);
    float2*  s_red= (float2*)(smraw + SO_RED);
    float2*  s_z  = (float2*)(smraw + SO_Z);
    float*   s_b  = (float*)(smraw + SO_B);

    const int tid  = threadIdx.x;
    const int row0 = 2 * blockIdx.x;

    // ---- prologue ----
    // proto_h -> fp16, transposed [d2][p]
    for (int i = tid; i < 128 * 128; i += NT2) {
        int d2 = i >> 7, p = i & 127;
        s_ph[d2 * 128 + p] = __floats2half2_rn(proto[p * (D_ + H_) + D_ + 2 * d2],
                                               proto[p * (D_ + H_) + D_ + 2 * d2 + 1]);
    }
    // W smem half (p<64), padded rows of 68 half2 (17x16B -> conflict-free LDS.128)
    for (int i = tid; i < 512 * 64; i += NT2) {
        int cp = i >> 6, p = i & 63;
        s_w[cp * 68 + p] = g_Whs[i];
    }
    // biases
    if (tid < 256) {
        s_b[0 * 256 + tid] = bfv[tid];
        s_b[1 * 256 + tid] = biv[tid];
        s_b[2 * 256 + tid] = bgv[tid];
        s_b[3 * 256 + tid] = bov[tid];
    }
    s_h[tid] = 0.0f;                      // [2][256] = 512 floats
    float c_reg = 0.0f;                   // cell state for (r = tid>>8, col = tid&255)
    __syncthreads();

    const int dq = tid >> 7;              // phase-K d-quarter
    const int pk = tid & 127;             // phase-K prototype
    const int r_ = tid >> 8;              // update/out row (0/1)
    const int col = tid & 255;            // update/out column
    const int cp = tid;                   // phase-G col-pair id

    const size_t TBH = (size_t)T_ * B_ * H_;
    const size_t BH  = (size_t)B_ * H_;

    for (int t = 0; t < T_; t++) {
        // ---- emit out[t-1] (h_{t-1} still in s_h) ----
        if (t > 0)
            __stcs(out + ((size_t)(t - 1) * B_ + row0 + r_) * H_ + col, s_h[r_ * 256 + col]);

        // ================= Phase K =================
        float d2x0 = 0.0f, d2x1 = 0.0f;
        if (dq == 0) {
            d2x0 = __ldcs(g_d2x + ((size_t)t * B_ + row0)     * P_ + pk);
            d2x1 = __ldcs(g_d2x + ((size_t)t * B_ + row0 + 1) * P_ + pk);
        }

        ull a0 = 0ULL, a1 = 0ULL;
        const __half2* php = s_ph + dq * 32 * 128 + pk;   // stride 128 per d2
        const float4* h0q = (const float4*)(s_h) + dq * 16;
        const float4* h1q = (const float4*)(s_h + 256) + dq * 16;
        #pragma unroll 4
        for (int i = 0; i < 16; i++) {
            float2 pa = __half22float2(php[(2 * i) * 128]);
            float2 pb = __half22float2(php[(2 * i + 1) * 128]);
            float4 u = h0q[i], v = h1q[i];
            ull ppA = pk2(pa.x, pa.y), ppB = pk2(pb.x, pb.y);
            ull dA0 = ffma2(ppA, NEG1X2, pk2(u.x, u.y)); a0 = ffma2(dA0, dA0, a0);
            ull dB0 = ffma2(ppB, NEG1X2, pk2(u.z, u.w)); a0 = ffma2(dB0, dB0, a0);
            ull dA1 = ffma2(ppA, NEG1X2, pk2(v.x, v.y)); a1 = ffma2(dA1, dA1, a1);
            ull dB1 = ffma2(ppB, NEG1X2, pk2(v.z, v.w)); a1 = ffma2(dB1, dB1, a1);
        }
        float s0a, s0b, s1a, s1b;
        upk2(a0, s0a, s0b); upk2(a1, s1a, s1b);
        float s0 = s0a + s0b, s1 = s1a + s1b;

        if (dq) s_red[(dq - 1) * 128 + pk] = make_float2(s0, s1);
        __syncthreads();                                        // sync A
        if (dq == 0) {
            float2 r1 = s_red[pk], r2 = s_red[128 + pk], r3 = s_red[256 + pk];
            float k0 = __expf(-(d2x0 + s0 + r1.x + r2.x + r3.x));
            float k1 = __expf(-(d2x1 + s1 + r1.y + r2.y + r3.y));
            ((float4*)s_kq)[pk] = make_float4(k0, k0, k1, k1);
        }
        __syncthreads();                                        // sync D: kq ready

        // ================= Phase G =================
        // prefetch streamed W half (p 64..127): 16 coalesced uint4
        uint4 wst[16];
        {
            const uint4* wsp = (const uint4*)g_Wst + cp;        // stride 512 per pq
            #pragma unroll
            for (int q = 0; q < 16; q++) wst[q] = __ldcg(wsp + q * 512);
        }
        ull acc0 = 0ULL, acc1 = 0ULL;
        const ulonglong2* kq2 = (const ulonglong2*)s_kq;        // [p]: {k0,k0},{k1,k1}
        // smem half: p 0..63
        {
            const uint4* ws4 = (const uint4*)(s_w + cp * 68);   // 16 x uint4 (4 p each)
            #pragma unroll 4
            for (int c8 = 0; c8 < 16; c8++) {
                uint4 w = ws4[c8];
                #pragma unroll
                for (int q2 = 0; q2 < 4; q2++) {
                    unsigned wu = (&w.x)[q2];
                    float2 wf = __half22float2(*reinterpret_cast<__half2*>(&wu));
                    ulonglong2 kk = kq2[c8 * 4 + q2];
                    ull wpk = pk2(wf.x, wf.y);
                    acc0 = ffma2(kk.x, wpk, acc0);
                    acc1 = ffma2(kk.y, wpk, acc1);
                }
            }
        }
        // streamed half: p 64..127
        #pragma unroll 4
        for (int c8 = 0; c8 < 16; c8++) {
            uint4 w = wst[c8];
            #pragma unroll
            for (int q2 = 0; q2 < 4; q2++) {
                unsigned wu = (&w.x)[q2];
                float2 wf = __half22float2(*reinterpret_cast<__half2*>(&wu));
                ulonglong2 kk = kq2[64 + c8 * 4 + q2];
                ull wpk = pk2(wf.x, wf.y);
                acc0 = ffma2(kk.x, wpk, acc0);
                acc1 = ffma2(kk.y, wpk, acc1);
            }
        }
        {
            float z00, z01, z10, z11;
            upk2(acc0, z00, z01);   // row0: cols 2c, 2c+1
            upk2(acc1, z10, z11);   // row1
            int g = cp >> 7, c = cp & 127;
            s_z[(g * 2 + 0) * 128 + c] = make_float2(z00, z01);
            s_z[(g * 2 + 1) * 128 + c] = make_float2(z10, z11);
        }
        __syncthreads();                                        // sync B: z ready

        // ================= Update =================
        {
            const float* zf = (const float*)s_z;
            float zF = zf[(0 * 2 + r_) * 256 + col] + s_b[0 * 256 + col];
            float zI = zf[(1 * 2 + r_) * 256 + col] + s_b[1 * 256 + col];
            float zG = zf[(2 * 2 + r_) * 256 + col] + s_b[2 * 256 + col];
            float zO = zf[(3 * 2 + r_) * 256 + col] + s_b[3 * 256 + col];
            float f = sigmf(zF), i = sigmf(zI), g = tanhf(zG), o = sigmf(zO);
            c_reg = f * c_reg + i * g;
            float h = o * tanhf(c_reg);
            __syncthreads();                                    // sync C: K-phase done with old s_h
            s_h[r_ * 256 + col] = h;
        }
        __syncthreads();                                        // h ready for next step
    }

    // ---- epilogue: out[T-1], hx, cx ----
    {
        float h = s_h[r_ * 256 + col];
        size_t row = row0 + r_;
        __stcs(out + ((size_t)(T_ - 1) * B_ + row) * H_ + col, h);
        __stcs(out + TBH + row * H_ + col, h);
        __stcs(out + TBH + BH + row * H_ + col, c_reg);
    }
}

// =====================================================================
// launch
// =====================================================================
extern "C" void kernel_launch(void* const* d_in, const int* in_sizes, int n_in,
                              void* d_out, int out_size) {
    const float* x     = (const float*)d_in[0];
    const float* proto = (const float*)d_in[1];
    const float* Wf    = (const float*)d_in[2];
    const float* bf    = (const float*)d_in[3];
    const float* Wi    = (const float*)d_in[4];
    const float* bi    = (const float*)d_in[5];
    const float* Wg    = (const float*)d_in[6];
    const float* bg    = (const float*)d_in[7];
    const float* Wo    = (const float*)d_in[8];
    const float* bo    = (const float*)d_in[9];
    float* out = (float*)d_out;

    cudaFuncSetAttribute(d2x_kernel,   cudaFuncAttributeMaxDynamicSharedMemorySize, D2X_SMEM);
    cudaFuncSetAttribute(qlstm_kernel, cudaFuncAttributeMaxDynamicSharedMemorySize, MAIN_SMEM);

    prep_kernel<<<NBLK, NT2>>>(Wf, Wi, Wg, Wo);
    d2x_kernel<<<dim3(T_, B_ / 16), NT1, D2X_SMEM>>>(x, proto);
    qlstm_kernel<<<NBLK, NT2, MAIN_SMEM>>>(proto, bf, bi, bg, bo, out);
}

// round 12
// speedup vs baseline: 3.6502x; 1.0372x over previous
#include <cuda_runtime.h>
#include <cuda_fp16.h>

#define T_ 512
#define B_ 256
#define D_ 128
#define H_ 256
#define P_ 128
#define NBLK 128
#define NT1 256
#define NT2 1024
#define PPAD 132

// ---------------- device scratch (static globals; no allocation) ----------------
__device__ float   g_d2x[T_ * B_ * P_];    // 64 MB: x-part of RBF distances
__device__ __half2 g_Whs[512 * 64];        // W fp16, smem-resident half: [cp][p<64]
__device__ __half2 g_Wst[512 * 64];        // W fp16, streamed half: [(p-64)/4][cp][p&3]

typedef unsigned long long ull;

__device__ __forceinline__ ull pk2(float a, float b) {
    ull r; asm("mov.b64 %0, {%1, %2};" : "=l"(r) : "f"(a), "f"(b)); return r;
}
__device__ __forceinline__ void upk2(ull v, float& a, float& b) {
    asm("mov.b64 {%0, %1}, %2;" : "=f"(a), "=f"(b) : "l"(v));
}
__device__ __forceinline__ ull ffma2(ull a, ull b, ull c) {
    ull d; asm("fma.rn.f32x2 %0, %1, %2, %3;" : "=l"(d) : "l"(a), "l"(b), "l"(c)); return d;
}
__device__ __forceinline__ ull h2tof2(unsigned u) {
    __half2 h = *reinterpret_cast<__half2*>(&u);
    float2 f = __half22float2(h);
    return pk2(f.x, f.y);
}
#define NEG1X2 0xBF800000BF800000ULL

__device__ __forceinline__ float sigmf(float x) { return 1.0f / (1.0f + __expf(-x)); }

// =====================================================================
// Kernel 0: pack W into fp16 col-pair layouts.
// =====================================================================
__global__ void __launch_bounds__(512) prep_kernel(
    const float* __restrict__ Wf, const float* __restrict__ Wi,
    const float* __restrict__ Wg, const float* __restrict__ Wo)
{
    int i = blockIdx.x * 512 + threadIdx.x;          // 128 x 512 = 65536
    int g = i >> 14, c = (i >> 7) & 127, p = i & 127;
    const float* W = (g == 0) ? Wf : (g == 1) ? Wi : (g == 2) ? Wg : Wo;
    __half2 v = __floats2half2_rn(W[(2 * c) * P_ + p], W[(2 * c + 1) * P_ + p]);
    int cp = g * 128 + c;
    if (p < 64) g_Whs[cp * 64 + p] = v;
    else        g_Wst[((p - 64) >> 2) * 2048 + cp * 4 + (p & 3)] = v;
}

// =====================================================================
// Kernel 1: d2x[t][b][p] (unchanged, proven)
// =====================================================================
#define D2X_SMEM ((P_ * PPAD + 16 * D_) * 4)

__global__ void __launch_bounds__(NT1) d2x_kernel(const float* __restrict__ x,
                                                  const float* __restrict__ proto) {
    extern __shared__ float sm[];
    float* ps = sm;
    float* xs = sm + P_ * PPAD;
    const int t = blockIdx.x, b0 = blockIdx.y * 16;
    const int tid = threadIdx.x;

    for (int i = tid; i < P_ * D_; i += NT1) {
        int p = i >> 7, d = i & 127;
        ps[p * PPAD + d] = proto[p * (D_ + H_) + d];
    }
    for (int i = tid; i < 16 * D_; i += NT1) {
        int bb = i >> 7, d = i & 127;
        xs[i] = x[((size_t)(t * B_) + b0 + bb) * D_ + d];
    }
    __syncthreads();

    const int p = tid & 127, bg = tid >> 7;
    ull acc[8];
    #pragma unroll
    for (int bb = 0; bb < 8; bb++) acc[bb] = 0ULL;
    const float4* pp = (const float4*)(ps + p * PPAD);
    const float*  xb = xs + bg * 8 * D_;

    #pragma unroll 4
    for (int i = 0; i < 32; i++) {
        float4 pv = pp[i];
        ull pA = pk2(pv.x, pv.y), pB = pk2(pv.z, pv.w);
        #pragma unroll
        for (int bb = 0; bb < 8; bb++) {
            float4 xv = *(const float4*)(xb + bb * D_ + 4 * i);
            ull dA = ffma2(pA, NEG1X2, pk2(xv.x, xv.y));
            ull dB = ffma2(pB, NEG1X2, pk2(xv.z, xv.w));
            acc[bb] = ffma2(dA, dA, acc[bb]);
            acc[bb] = ffma2(dB, dB, acc[bb]);
        }
    }
    #pragma unroll
    for (int bb = 0; bb < 8; bb++) {
        float a, b; upk2(acc[bb], a, b);
        g_d2x[((size_t)t * B_ + b0 + bg * 8 + bb) * P_ + p] = a + b;
    }
}

// =====================================================================
// Kernel 2: barrier-free recurrent kernel. 128 blocks x 1024 threads.
// Phase K (dot form, FULL 256 dims): tid -> (p = tid>>3, sub = tid&7;
//   row = sub&1, dq = sub>>1; each dq covers 64 h-dims).
//   d2_h = |h|^2 + |p~|^2 - 2 h.p~ ; shfl reduce over dq (same warp).
// Phase G: ph2 = (tid>>5)&1 warp-uniform; cp = (tid>>6)*32 + (tid&31).
// Update: tid<512 -> (r = tid>>8, col = tid&255).
// =====================================================================
// smem layout (byte offsets)
#define SO_PH   0                       // proto_h fp16 [128 p][4 dq][9 uint4 (8 data+1 pad)] -> stride 35 u4: 71680 B
#define SO_W    71680                   // W smem half [512 cp][68 pad h2]: 139264 B
#define SO_H    210944                  // h [2 row][4 dq][68 pad f32]: 2176 B
#define SO_KQ   213120                  // kq splat {k0,k0,k1,k1}/p + 16B pad at p=64: 2064 B
#define SO_Z    215184                  // z [2 ph2][8 gr][256] f32: 16384 B
#define SO_PN   231568                  // |p~|^2 [128] f32: 512 B
#define SO_HNP  232080                  // |h|^2 warp partials [16] f32: 64 B
#define MAIN_SMEM 232144                // < 232448 (227 KB)

__global__ void __launch_bounds__(NT2, 1) qlstm_kernel(
    const float* __restrict__ proto,
    const float* __restrict__ bfv, const float* __restrict__ biv,
    const float* __restrict__ bgv, const float* __restrict__ bov,
    float* __restrict__ out)
{
    extern __shared__ char smraw[];
    __half2* s_ph  = (__half2*)(smraw + SO_PH);   // addressed via uint4 stride 35
    __half2* s_w   = (__half2*)(smraw + SO_W);
    float*   s_h   = (float*)(smraw + SO_H);      // [2][4][68]
    float*   s_zf  = (float*)(smraw + SO_Z);
    float*   s_pn  = (float*)(smraw + SO_PN);
    float*   s_hnp = (float*)(smraw + SO_HNP);

    const int tid  = threadIdx.x;
    const int row0 = 2 * blockIdx.x;

    // ---- prologue ----
    // proto_h fp16: element (p, d2) -> half2 idx p*140 + (d2>>5)*36 + (d2&31)
    for (int i = tid; i < 128 * 128; i += NT2) {
        int p = i >> 7, d2 = i & 127;
        s_ph[p * 140 + (d2 >> 5) * 36 + (d2 & 31)] =
            __floats2half2_rn(proto[p * (D_ + H_) + D_ + 2 * d2],
                              proto[p * (D_ + H_) + D_ + 2 * d2 + 1]);
    }
    for (int i = tid; i < 512 * 64; i += NT2) {
        int cp = i >> 6, pp = i & 63;
        s_w[cp * 68 + pp] = g_Whs[i];
    }
    if (tid < 544) s_h[tid] = 0.0f;               // [2][4][68] incl. pads
    if (tid < 16)  s_hnp[tid] = 0.0f;
    float c_reg = 0.0f;
    __syncthreads();

    if (tid < 128) {      // |p~|^2 from ROUNDED prototypes, all 256 dims (exact algebra)
        float pnv = 0.0f;
        const uint4* pr = (const uint4*)s_ph + tid * 35;
        #pragma unroll
        for (int dq = 0; dq < 4; dq++) {
            #pragma unroll
            for (int j = 0; j < 8; j++) {
                uint4 v = pr[dq * 9 + j];
                #pragma unroll
                for (int q = 0; q < 4; q++) {
                    float2 f = __half22float2(*reinterpret_cast<__half2*>(&(&v.x)[q]));
                    pnv += f.x * f.x + f.y * f.y;
                }
            }
        }
        s_pn[tid] = pnv;
    }
    __syncthreads();

    // phase-K mapping
    const int pK   = tid >> 3;
    const int sub  = tid & 7;
    const int rowK = sub & 1;
    const int dqK  = sub >> 1;
    // phase-G mapping (warp-uniform ph2)
    const int ph2 = (tid >> 5) & 1;
    const int cpG = ((tid >> 6) << 5) | (tid & 31);
    const int gG  = cpG >> 7, cG = cpG & 127;
    const float* bp = (gG == 0) ? bfv : (gG == 1) ? biv : (gG == 2) ? bgv : bov;
    const ull bias2 = pk2(bp[2 * cG], bp[2 * cG + 1]);
    // update mapping
    const int r_  = tid >> 8;       // valid for tid<512
    const int col = tid & 255;
    const int hIdx = r_ * 272 + ((col >> 6) * 68) + (col & 63);   // s_h index for (r_, col)

    const char* kqBase = smraw + SO_KQ;
    const char* kqP    = kqBase + ph2 * 1040;     // streamed half starts at p=64 (+16B pad)
    const size_t TBH = (size_t)T_ * B_ * H_;
    const size_t BH  = (size_t)B_ * H_;

    for (int t = 0; t < T_; t++) {
        // ================= Phase K: dot(h_row, proto_p) over 64 dims/thread =================
        {
            ull acc = 0ULL;
            const uint4*  ph4 = (const uint4*)s_ph + pK * 35 + dqK * 9;
            const float4* h4  = (const float4*)s_h + rowK * 68 + dqK * 17;
            #pragma unroll
            for (int i = 0; i < 8; i++) {
                uint4 pv = ph4[i];
                float4 ha = h4[2 * i], hb = h4[2 * i + 1];
                acc = ffma2(pk2(ha.x, ha.y), h2tof2(pv.x), acc);
                acc = ffma2(pk2(ha.z, ha.w), h2tof2(pv.y), acc);
                acc = ffma2(pk2(hb.x, hb.y), h2tof2(pv.z), acc);
                acc = ffma2(pk2(hb.z, hb.w), h2tof2(pv.w), acc);
            }
            float da, db; upk2(acc, da, db);
            float dot = da + db;
            dot += __shfl_xor_sync(0xFFFFFFFFu, dot, 2);
            dot += __shfl_xor_sync(0xFFFFFFFFu, dot, 4);
            if (sub < 2) {
                float d2xv = __ldcs(g_d2x + ((size_t)t * B_ + row0 + rowK) * P_ + pK);
                const float4* hp = (const float4*)s_hnp + rowK * 2;
                float4 A = hp[0], Bq = hp[1];
                float hn = ((A.x + A.y) + (A.z + A.w)) + ((Bq.x + Bq.y) + (Bq.z + Bq.w));
                float k = __expf(-(d2xv + hn + s_pn[pK] - 2.0f * dot));
                *(float2*)(kqBase + pK * 16 + ((pK >> 6) << 4) + rowK * 8) = make_float2(k, k);
            }
        }
        __syncthreads();                                   // kq ready

        // ================= Phase G =================
        {
            ull acc0 = (ph2 == 0) ? bias2 : 0ULL;          // bias folded into resident half
            ull acc1 = acc0;
            if (ph2 == 0) {
                const uint4* w4 = (const uint4*)s_w + cpG * 17;
                #pragma unroll 4
                for (int c8 = 0; c8 < 16; c8++) {
                    uint4 w = w4[c8];
                    #pragma unroll
                    for (int q2 = 0; q2 < 4; q2++) {
                        ull wpk = h2tof2((&w.x)[q2]);
                        ulonglong2 kk = *(const ulonglong2*)(kqP + (c8 * 4 + q2) * 16);
                        acc0 = ffma2(kk.x, wpk, acc0);
                        acc1 = ffma2(kk.y, wpk, acc1);
                    }
                }
            } else {
                const uint4* wg = (const uint4*)g_Wst + cpG;
                #pragma unroll 4
                for (int c8 = 0; c8 < 16; c8++) {
                    uint4 w = __ldcg(wg + c8 * 512);
                    #pragma unroll
                    for (int q2 = 0; q2 < 4; q2++) {
                        ull wpk = h2tof2((&w.x)[q2]);
                        ulonglong2 kk = *(const ulonglong2*)(kqP + (c8 * 4 + q2) * 16);
                        acc0 = ffma2(kk.x, wpk, acc0);
                        acc1 = ffma2(kk.y, wpk, acc1);
                    }
                }
            }
            float z00, z01, z10, z11;
            upk2(acc0, z00, z01);
            upk2(acc1, z10, z11);
            ((float2*)s_zf)[(ph2 * 8 + gG * 2 + 0) * 128 + cG] = make_float2(z00, z01);
            ((float2*)s_zf)[(ph2 * 8 + gG * 2 + 1) * 128 + cG] = make_float2(z10, z11);
        }
        __syncthreads();                                   // z ready

        // ================= Update (tid < 512) =================
        if (tid < 512) {
            float zF = s_zf[(0 + r_) * 256 + col] + s_zf[(8 + 0 + r_) * 256 + col];
            float zI = s_zf[(2 + r_) * 256 + col] + s_zf[(8 + 2 + r_) * 256 + col];
            float zG = s_zf[(4 + r_) * 256 + col] + s_zf[(8 + 4 + r_) * 256 + col];
            float zO = s_zf[(6 + r_) * 256 + col] + s_zf[(8 + 6 + r_) * 256 + col];
            float f = sigmf(zF), i = sigmf(zI), g = tanhf(zG), o = sigmf(zO);
            c_reg = f * c_reg + i * g;
            float h = o * tanhf(c_reg);
            s_h[hIdx] = h;
            __stcs(out + ((size_t)t * B_ + row0 + r_) * H_ + col, h);
            float h2v = h * h;                             // |h|^2 warp partials
            #pragma unroll
            for (int off = 16; off; off >>= 1) h2v += __shfl_xor_sync(0xFFFFFFFFu, h2v, off);
            if ((tid & 31) == 0) s_hnp[tid >> 5] = h2v;
        }
        __syncthreads();                                   // h, hnp ready
    }

    // ---- epilogue: hx, cx ----
    if (tid < 512) {
        float h = s_h[hIdx];
        size_t row = row0 + r_;
        __stcs(out + TBH + row * H_ + col, h);
        __stcs(out + TBH + BH + row * H_ + col, c_reg);
    }
}

// =====================================================================
// launch
// =====================================================================
extern "C" void kernel_launch(void* const* d_in, const int* in_sizes, int n_in,
                              void* d_out, int out_size) {
    const float* x     = (const float*)d_in[0];
    const float* proto = (const float*)d_in[1];
    const float* Wf    = (const float*)d_in[2];
    const float* bf    = (const float*)d_in[3];
    const float* Wi    = (const float*)d_in[4];
    const float* bi    = (const float*)d_in[5];
    const float* Wg    = (const float*)d_in[6];
    const float* bg    = (const float*)d_in[7];
    const float* Wo    = (const float*)d_in[8];
    const float* bo    = (const float*)d_in[9];
    float* out = (float*)d_out;

    cudaFuncSetAttribute(d2x_kernel,   cudaFuncAttributeMaxDynamicSharedMemorySize, D2X_SMEM);
    cudaFuncSetAttribute(qlstm_kernel, cudaFuncAttributeMaxDynamicSharedMemorySize, MAIN_SMEM);

    prep_kernel<<<NBLK, 512>>>(Wf, Wi, Wg, Wo);
    d2x_kernel<<<dim3(T_, B_ / 16), NT1, D2X_SMEM>>>(x, proto);
    qlstm_kernel<<<NBLK, NT2, MAIN_SMEM>>>(proto, bf, bi, bg, bo, out);
}